// round 2
// baseline (speedup 1.0000x reference)
#include <cuda_runtime.h>
#include <math.h>

// Problem constants (fixed shapes from setup_inputs)
#define NB 256
#define NJ 24
#define TDIM 1024
#define NF 8
// loss scale: 1 / (B * F * J * 3)
#define LOSS_SCALE (1.0f / 147456.0f)

// Ancestor path (root -> j, inclusive) per joint, padded; LEN = path length.
__device__ __constant__ int c_PATH[NJ][9] = {
    {0,0,0,0,0,0,0,0,0},          // 0
    {0,1,0,0,0,0,0,0,0},          // 1
    {0,2,0,0,0,0,0,0,0},          // 2
    {0,3,0,0,0,0,0,0,0},          // 3
    {0,1,4,0,0,0,0,0,0},          // 4
    {0,2,5,0,0,0,0,0,0},          // 5
    {0,3,6,0,0,0,0,0,0},          // 6
    {0,1,4,7,0,0,0,0,0},          // 7
    {0,2,5,8,0,0,0,0,0},          // 8
    {0,3,6,9,0,0,0,0,0},          // 9
    {0,1,4,7,10,0,0,0,0},         // 10
    {0,2,5,8,11,0,0,0,0},         // 11
    {0,3,6,9,12,0,0,0,0},         // 12
    {0,3,6,9,13,0,0,0,0},         // 13
    {0,3,6,9,14,0,0,0,0},         // 14
    {0,3,6,9,12,15,0,0,0},        // 15
    {0,3,6,9,13,16,0,0,0},        // 16
    {0,3,6,9,14,17,0,0,0},        // 17
    {0,3,6,9,13,16,18,0,0},       // 18
    {0,3,6,9,14,17,19,0,0},       // 19
    {0,3,6,9,13,16,18,20,0},      // 20
    {0,3,6,9,14,17,19,21,0},      // 21
    {0,3,6,9,13,16,18,20,22},     // 22
    {0,3,6,9,14,17,19,21,23}      // 23
};
__device__ __constant__ int c_LEN[NJ] = {
    1,2,2,2,3,3,3,4,4,4,5,5,5,5,5,6,6,6,7,7,8,8,9,9
};
// linspace(0, 1023, 8).astype(int32)
__device__ __constant__ int c_FIDX[NF] = {0,146,292,438,584,730,876,1023};

struct Quat { float w, x, y, z; };

__device__ __forceinline__ Quat qmul(const Quat a, const Quat b) {
    Quat r;
    r.w = a.w*b.w - a.x*b.x - a.y*b.y - a.z*b.z;
    r.x = a.w*b.x + a.x*b.w + a.y*b.z - a.z*b.y;
    r.y = a.w*b.y - a.x*b.z + a.y*b.w + a.z*b.x;
    r.z = a.w*b.z + a.x*b.y - a.y*b.x + a.z*b.w;
    return r;
}

// rotate v by quaternion q (wxyz):  v + w*t + cross(xyz, t),  t = 2*cross(xyz, v)
__device__ __forceinline__ void qrot(const Quat q, float vx, float vy, float vz,
                                     float& ox, float& oy, float& oz) {
    float tx = 2.0f * (q.y*vz - q.z*vy);
    float ty = 2.0f * (q.z*vx - q.x*vz);
    float tz = 2.0f * (q.x*vy - q.y*vx);
    ox = vx + q.w*tx + (q.y*tz - q.z*ty);
    oy = vy + q.w*ty + (q.z*tx - q.x*tz);
    oz = vz + q.w*tz + (q.x*ty - q.y*tx);
}

// 6d (Zhou et al. Gram-Schmidt) -> rotation matrix -> quaternion (pytorch3d branchless)
__device__ __forceinline__ Quat quat_from_6d(const float v[6]) {
    float a1x = v[0], a1y = v[1], a1z = v[2];
    float a2x = v[3], a2y = v[4], a2z = v[5];
    float n1 = sqrtf(a1x*a1x + a1y*a1y + a1z*a1z);
    float i1 = 1.0f / fmaxf(n1, 1e-8f);
    float b1x = a1x*i1, b1y = a1y*i1, b1z = a1z*i1;
    float d = b1x*a2x + b1y*a2y + b1z*a2z;
    float ux = a2x - d*b1x, uy = a2y - d*b1y, uz = a2z - d*b1z;
    float n2 = sqrtf(ux*ux + uy*uy + uz*uz);
    float i2 = 1.0f / fmaxf(n2, 1e-8f);
    float b2x = ux*i2, b2y = uy*i2, b2z = uz*i2;
    float b3x = b1y*b2z - b1z*b2y;
    float b3y = b1z*b2x - b1x*b2z;
    float b3z = b1x*b2y - b1y*b2x;
    // matrix rows: b1, b2, b3
    float m00 = b1x, m01 = b1y, m02 = b1z;
    float m10 = b2x, m11 = b2y, m12 = b2z;
    float m20 = b3x, m21 = b3y, m22 = b3z;

    float qa0 = sqrtf(fmaxf(1.0f + m00 + m11 + m22, 0.0f));
    float qa1 = sqrtf(fmaxf(1.0f + m00 - m11 - m22, 0.0f));
    float qa2 = sqrtf(fmaxf(1.0f - m00 + m11 - m22, 0.0f));
    float qa3 = sqrtf(fmaxf(1.0f - m00 - m11 + m22, 0.0f));

    // first-argmax semantics (strict >)
    int k = 0; float best = qa0;
    if (qa1 > best) { k = 1; best = qa1; }
    if (qa2 > best) { k = 2; best = qa2; }
    if (qa3 > best) { k = 3; best = qa3; }

    float w, x, y, z, qa;
    if (k == 0) { qa = qa0; w = qa0*qa0;  x = m21 - m12; y = m02 - m20; z = m10 - m01; }
    else if (k == 1) { qa = qa1; w = m21 - m12; x = qa1*qa1;  y = m10 + m01; z = m02 + m20; }
    else if (k == 2) { qa = qa2; w = m02 - m20; x = m10 + m01; y = qa2*qa2;  z = m12 + m21; }
    else             { qa = qa3; w = m10 - m01; x = m20 + m02; y = m21 + m12; z = qa3*qa3;  }

    float inv = 1.0f / (2.0f * fmaxf(qa, 0.1f));
    Quat q; q.w = w*inv; q.x = x*inv; q.y = y*inv; q.z = z*inv;
    return q;
}

__global__ void fk_zero_kernel(float* __restrict__ out) {
    out[0] = 0.0f;
}

// One block per (b, f) pair. 64 threads.
//   phase 1: threads 0..47 = (side, joint): gather 6d, compute local quat -> smem
//   phase 2: threads 0..47: global quat via ancestor-path product -> smem
//   phase 3: threads 0..23 = joint: position diff via path sum, squared; warp-0 reduce
__global__ void __launch_bounds__(64, 16)
fk_loss_kernel(const float* __restrict__ pred,
               const float* __restrict__ targ,
               const float* __restrict__ offsets,
               float* __restrict__ out) {
    __shared__ float s_lq[2][NJ][4];
    __shared__ float s_gq[2][NJ][4];

    const int tid = threadIdx.x;
    const int b = blockIdx.x >> 3;
    const int f = blockIdx.x & 7;
    const int fi = c_FIDX[f];

    // ---- phase 1: local quats ----
    if (tid < 2 * NJ) {
        const int s = tid / NJ;          // 0 = pred, 1 = target
        const int j = tid - s * NJ;
        const float* __restrict__ ptr = s ? targ : pred;
        const int base = ((b * NJ + j) * 6) * TDIM + fi;
        float v[6];
#pragma unroll
        for (int c = 0; c < 6; ++c)
            v[c] = __ldg(ptr + base + c * TDIM);
        Quat q = quat_from_6d(v);
        s_lq[s][j][0] = q.w; s_lq[s][j][1] = q.x;
        s_lq[s][j][2] = q.y; s_lq[s][j][3] = q.z;
    }
    __syncthreads();

    // ---- phase 2: global quats (left-fold along ancestor path, same FP order as ref) ----
    if (tid < 2 * NJ) {
        const int s = tid / NJ;
        const int j = tid - s * NJ;
        Quat q = { s_lq[s][0][0], s_lq[s][0][1], s_lq[s][0][2], s_lq[s][0][3] };
        const int len = c_LEN[j];
        for (int d2 = 1; d2 < len; ++d2) {
            const int a = c_PATH[j][d2];
            Quat l = { s_lq[s][a][0], s_lq[s][a][1], s_lq[s][a][2], s_lq[s][a][3] };
            q = qmul(q, l);
        }
        s_gq[s][j][0] = q.w; s_gq[s][j][1] = q.x;
        s_gq[s][j][2] = q.y; s_gq[s][j][3] = q.z;
    }
    __syncthreads();

    // ---- phase 3: position diff (root translation cancels; joint 0 contributes 0) ----
    float acc = 0.0f;
    if (tid < NJ) {
        const int j = tid;
        float px = 0.f, py = 0.f, pz = 0.f;
        float qx2 = 0.f, qy2 = 0.f, qz2 = 0.f;
        const int len = c_LEN[j];
        for (int d2 = 1; d2 < len; ++d2) {
            const int a = c_PATH[j][d2];
            const int p = c_PATH[j][d2 - 1];
            const float ox = __ldg(offsets + a * 3 + 0);
            const float oy = __ldg(offsets + a * 3 + 1);
            const float oz = __ldg(offsets + a * 3 + 2);
            Quat qp = { s_gq[0][p][0], s_gq[0][p][1], s_gq[0][p][2], s_gq[0][p][3] };
            Quat qt = { s_gq[1][p][0], s_gq[1][p][1], s_gq[1][p][2], s_gq[1][p][3] };
            float rx, ry, rz;
            qrot(qp, ox, oy, oz, rx, ry, rz);  px  += rx; py  += ry; pz  += rz;
            qrot(qt, ox, oy, oz, rx, ry, rz);  qx2 += rx; qy2 += ry; qz2 += rz;
        }
        const float dx = px - qx2, dy = py - qy2, dz = pz - qz2;
        acc = dx*dx + dy*dy + dz*dz;
    }

    // ---- block reduce (only warp 0 holds nonzero values) + atomic ----
    if (tid < 32) {
#pragma unroll
        for (int o = 16; o > 0; o >>= 1)
            acc += __shfl_down_sync(0xffffffffu, acc, o);
        if (tid == 0)
            atomicAdd(out, acc * LOSS_SCALE);
    }
}

extern "C" void kernel_launch(void* const* d_in, const int* in_sizes, int n_in,
                              void* d_out, int out_size) {
    const float* pred    = (const float*)d_in[0];   // (256, 24, 6, 1024)
    const float* targ    = (const float*)d_in[1];   // (256, 24, 6, 1024)
    // d_in[2] = root_translation — cancels in the position diff, never read
    const float* offsets = (const float*)d_in[3];   // (24, 3)
    float* out = (float*)d_out;

    fk_zero_kernel<<<1, 1>>>(out);
    fk_loss_kernel<<<NB * NF, 64>>>(pred, targ, offsets, out);
}

// round 4
// speedup vs baseline: 1.1248x; 1.1248x over previous
#include <cuda_runtime.h>
#include <math.h>

// Problem constants (fixed shapes from setup_inputs)
#define NB 256
#define NJ 24
#define TDIM 1024
#define NF 8
// loss scale: 1 / (B * F * J * 3)
#define LOSS_SCALE (1.0f / 147456.0f)

// Ancestor path (root -> j, inclusive) per joint, padded; LEN = path length.
__device__ __constant__ int c_PATH[NJ][9] = {
    {0,0,0,0,0,0,0,0,0},          // 0
    {0,1,0,0,0,0,0,0,0},          // 1
    {0,2,0,0,0,0,0,0,0},          // 2
    {0,3,0,0,0,0,0,0,0},          // 3
    {0,1,4,0,0,0,0,0,0},          // 4
    {0,2,5,0,0,0,0,0,0},          // 5
    {0,3,6,0,0,0,0,0,0},          // 6
    {0,1,4,7,0,0,0,0,0},          // 7
    {0,2,5,8,0,0,0,0,0},          // 8
    {0,3,6,9,0,0,0,0,0},          // 9
    {0,1,4,7,10,0,0,0,0},         // 10
    {0,2,5,8,11,0,0,0,0},         // 11
    {0,3,6,9,12,0,0,0,0},         // 12
    {0,3,6,9,13,0,0,0,0},         // 13
    {0,3,6,9,14,0,0,0,0},         // 14
    {0,3,6,9,12,15,0,0,0},        // 15
    {0,3,6,9,13,16,0,0,0},        // 16
    {0,3,6,9,14,17,0,0,0},        // 17
    {0,3,6,9,13,16,18,0,0},       // 18
    {0,3,6,9,14,17,19,0,0},       // 19
    {0,3,6,9,13,16,18,20,0},      // 20
    {0,3,6,9,14,17,19,21,0},      // 21
    {0,3,6,9,13,16,18,20,22},     // 22
    {0,3,6,9,14,17,19,21,23}      // 23
};
__device__ __constant__ int c_LEN[NJ] = {
    1,2,2,2,3,3,3,4,4,4,5,5,5,5,5,6,6,6,7,7,8,8,9,9
};
// linspace(0, 1023, 8).astype(int32)
__device__ __constant__ int c_FIDX[NF] = {0,146,292,438,584,730,876,1023};

struct Quat { float w, x, y, z; };

__device__ __forceinline__ Quat qmul(const Quat a, const Quat b) {
    Quat r;
    r.w = a.w*b.w - a.x*b.x - a.y*b.y - a.z*b.z;
    r.x = a.w*b.x + a.x*b.w + a.y*b.z - a.z*b.y;
    r.y = a.w*b.y - a.x*b.z + a.y*b.w + a.z*b.x;
    r.z = a.w*b.z + a.x*b.y - a.y*b.x + a.z*b.w;
    return r;
}

// rotate v by quaternion q (wxyz):  v + w*t + cross(xyz, t),  t = 2*cross(xyz, v)
__device__ __forceinline__ void qrot(const Quat q, float vx, float vy, float vz,
                                     float& ox, float& oy, float& oz) {
    float tx = 2.0f * (q.y*vz - q.z*vy);
    float ty = 2.0f * (q.z*vx - q.x*vz);
    float tz = 2.0f * (q.x*vy - q.y*vx);
    ox = vx + q.w*tx + (q.y*tz - q.z*ty);
    oy = vy + q.w*ty + (q.z*tx - q.x*tz);
    oz = vz + q.w*tz + (q.x*ty - q.y*tx);
}

// 6d (Zhou et al. Gram-Schmidt) -> rotation matrix -> quaternion (pytorch3d branchless)
__device__ __forceinline__ Quat quat_from_6d(const float v[6]) {
    float a1x = v[0], a1y = v[1], a1z = v[2];
    float a2x = v[3], a2y = v[4], a2z = v[5];
    float n1 = sqrtf(a1x*a1x + a1y*a1y + a1z*a1z);
    float i1 = 1.0f / fmaxf(n1, 1e-8f);
    float b1x = a1x*i1, b1y = a1y*i1, b1z = a1z*i1;
    float d = b1x*a2x + b1y*a2y + b1z*a2z;
    float ux = a2x - d*b1x, uy = a2y - d*b1y, uz = a2z - d*b1z;
    float n2 = sqrtf(ux*ux + uy*uy + uz*uz);
    float i2 = 1.0f / fmaxf(n2, 1e-8f);
    float b2x = ux*i2, b2y = uy*i2, b2z = uz*i2;
    float b3x = b1y*b2z - b1z*b2y;
    float b3y = b1z*b2x - b1x*b2z;
    float b3z = b1x*b2y - b1y*b2x;
    // matrix rows: b1, b2, b3
    float m00 = b1x, m01 = b1y, m02 = b1z;
    float m10 = b2x, m11 = b2y, m12 = b2z;
    float m20 = b3x, m21 = b3y, m22 = b3z;

    float qa0 = sqrtf(fmaxf(1.0f + m00 + m11 + m22, 0.0f));
    float qa1 = sqrtf(fmaxf(1.0f + m00 - m11 - m22, 0.0f));
    float qa2 = sqrtf(fmaxf(1.0f - m00 + m11 - m22, 0.0f));
    float qa3 = sqrtf(fmaxf(1.0f - m00 - m11 + m22, 0.0f));

    // first-argmax semantics (strict >)
    int k = 0; float best = qa0;
    if (qa1 > best) { k = 1; best = qa1; }
    if (qa2 > best) { k = 2; best = qa2; }
    if (qa3 > best) { k = 3; best = qa3; }

    float w, x, y, z, qa;
    if (k == 0) { qa = qa0; w = qa0*qa0;  x = m21 - m12; y = m02 - m20; z = m10 - m01; }
    else if (k == 1) { qa = qa1; w = m21 - m12; x = qa1*qa1;  y = m10 + m01; z = m02 + m20; }
    else if (k == 2) { qa = qa2; w = m02 - m20; x = m10 + m01; y = qa2*qa2;  z = m12 + m21; }
    else             { qa = qa3; w = m10 - m01; x = m20 + m02; y = m21 + m12; z = qa3*qa3;  }

    float inv = 1.0f / (2.0f * fmaxf(qa, 0.1f));
    Quat q; q.w = w*inv; q.x = x*inv; q.y = y*inv; q.z = z*inv;
    return q;
}

__global__ void fk_zero_kernel(float* __restrict__ out) {
    out[0] = 0.0f;
}

// One block per batch b. 384 threads = (f in 0..7) x (side in 0..1) x (joint in 0..23).
//   phase 1: ALL 384 threads gather 6 scattered scalars, compute local quat -> smem
//   phase 2: ALL 384 threads compute global quat via ancestor-path product -> smem
//   phase 3: 192 threads (f, joint) compute squared position diff; block reduce; 1 atomic
__global__ void __launch_bounds__(384, 2)
fk_loss_kernel(const float* __restrict__ pred,
               const float* __restrict__ targ,
               const float* __restrict__ offsets,
               float* __restrict__ out) {
    __shared__ float s_lq[NF][2][NJ][4];
    __shared__ float s_gq[NF][2][NJ][4];
    __shared__ float s_part[12];

    const int tid = threadIdx.x;
    const int b   = blockIdx.x;
    const int f   = tid / 48;
    const int r   = tid - f * 48;
    const int s   = r / NJ;          // 0 = pred, 1 = target
    const int j   = r - s * NJ;
    const int fi  = c_FIDX[f];

    // ---- phase 1: local quats (all 384 threads issue 6 independent LDGs) ----
    {
        const float* __restrict__ ptr = s ? targ : pred;
        const int base = ((b * NJ + j) * 6) * TDIM + fi;
        float v[6];
#pragma unroll
        for (int c = 0; c < 6; ++c)
            v[c] = __ldg(ptr + base + c * TDIM);
        Quat q = quat_from_6d(v);
        s_lq[f][s][j][0] = q.w; s_lq[f][s][j][1] = q.x;
        s_lq[f][s][j][2] = q.y; s_lq[f][s][j][3] = q.z;
    }
    __syncthreads();

    // ---- phase 2: global quats (left-fold along ancestor path, same FP order as ref) ----
    {
        Quat q = { s_lq[f][s][0][0], s_lq[f][s][0][1], s_lq[f][s][0][2], s_lq[f][s][0][3] };
        const int len = c_LEN[j];
        for (int d2 = 1; d2 < len; ++d2) {
            const int a = c_PATH[j][d2];
            Quat l = { s_lq[f][s][a][0], s_lq[f][s][a][1], s_lq[f][s][a][2], s_lq[f][s][a][3] };
            q = qmul(q, l);
        }
        s_gq[f][s][j][0] = q.w; s_gq[f][s][j][1] = q.x;
        s_gq[f][s][j][2] = q.y; s_gq[f][s][j][3] = q.z;
    }
    __syncthreads();

    // ---- phase 3: position diff (root translation cancels; joint 0 contributes 0) ----
    float acc = 0.0f;
    if (s == 0) {   // 192 threads: one per (f, j)
        float px = 0.f, py = 0.f, pz = 0.f;
        float tx2 = 0.f, ty2 = 0.f, tz2 = 0.f;
        const int len = c_LEN[j];
        for (int d2 = 1; d2 < len; ++d2) {
            const int a = c_PATH[j][d2];
            const int p = c_PATH[j][d2 - 1];
            const float ox = __ldg(offsets + a * 3 + 0);
            const float oy = __ldg(offsets + a * 3 + 1);
            const float oz = __ldg(offsets + a * 3 + 2);
            Quat qp = { s_gq[f][0][p][0], s_gq[f][0][p][1], s_gq[f][0][p][2], s_gq[f][0][p][3] };
            Quat qt = { s_gq[f][1][p][0], s_gq[f][1][p][1], s_gq[f][1][p][2], s_gq[f][1][p][3] };
            float rx, ry, rz;
            qrot(qp, ox, oy, oz, rx, ry, rz);  px  += rx; py  += ry; pz  += rz;
            qrot(qt, ox, oy, oz, rx, ry, rz);  tx2 += rx; ty2 += ry; tz2 += rz;
        }
        const float dx = px - tx2, dy = py - ty2, dz = pz - tz2;
        acc = dx*dx + dy*dy + dz*dz;
    }

    // ---- block reduce: warp shuffle -> smem partials -> thread 0 atomic ----
#pragma unroll
    for (int o = 16; o > 0; o >>= 1)
        acc += __shfl_down_sync(0xffffffffu, acc, o);
    const int wid  = tid >> 5;
    const int lane = tid & 31;
    if (lane == 0) s_part[wid] = acc;
    __syncthreads();
    if (tid == 0) {
        float total = 0.0f;
#pragma unroll
        for (int w = 0; w < 12; ++w) total += s_part[w];
        atomicAdd(out, total * LOSS_SCALE);
    }
}

extern "C" void kernel_launch(void* const* d_in, const int* in_sizes, int n_in,
                              void* d_out, int out_size) {
    const float* pred    = (const float*)d_in[0];   // (256, 24, 6, 1024)
    const float* targ    = (const float*)d_in[1];   // (256, 24, 6, 1024)
    // d_in[2] = root_translation — cancels in the position diff, never read
    const float* offsets = (const float*)d_in[3];   // (24, 3)
    float* out = (float*)d_out;

    fk_zero_kernel<<<1, 1>>>(out);
    fk_loss_kernel<<<NB, 384>>>(pred, targ, offsets, out);
}